// round 16
// baseline (speedup 1.0000x reference)
#include <cuda_runtime.h>
#include <cuda_fp16.h>
#include <cstdint>

// Problem constants
#define BATCH   2
#define NPTS    2048
#define CIN     64
#define COUT    128
#define GRIDV   12
#define NVOX    (GRIDV*GRIDV*GRIDV)   // 1728
#define NOFF    27
#define NGRP    4                     // offset groups: 7/7/7/6
#define TM      64                    // points per conv block
#define NTILE   (BATCH*NPTS/TM)       // 64 point tiles
#define NROWS   (BATCH*NVOX)          // 3456
#define ZROW    NROWS                 // dedicated zero row index
#define OUTN    (BATCH*NPTS*COUT)     // 524288

// Scratch (device globals; no allocation allowed).
// INVARIANT: g_aggH is all-zero at kernel_launch entry. It is zero-initialized
// at module load (static storage), and cleanup_kernel re-zeroes it at the END
// of every launch (after conv, its only reader, completes). Deterministic:
// every execution sees the same initial state and restores it.
__device__ __align__(16) unsigned char g_aggH[(NROWS + 1) * 128];  // fp16 agg rows (+zero row)
// W per offset: 16KB = [n][128B row], fp16, SW128-PRE-SWIZZLED
__device__ __align__(1024) unsigned char g_Wn[NOFF * 16384];

// ---------------------------------------------------------------------------
// Helpers
// ---------------------------------------------------------------------------
#define MBAR_INIT(a, c) \
    asm volatile("mbarrier.init.shared.b64 [%0], %1;" :: "r"(a), "r"(c) : "memory")
#define MBAR_EXPECT_TX(a, b) \
    asm volatile("mbarrier.arrive.expect_tx.shared.b64 _, [%0], %1;" :: "r"(a), "r"(b) : "memory")
#define BULK_G2S(dst, src, bytes, mbar) \
    asm volatile("cp.async.bulk.shared::cluster.global.mbarrier::complete_tx::bytes [%0], [%1], %2, [%3];" \
                 :: "r"(dst), "l"(src), "r"(bytes), "r"(mbar) : "memory")
#define RED_ADD_V2(addr, x, y) \
    asm volatile("red.global.add.v2.f32 [%0], {%1, %2};" :: "l"(addr), "f"(x), "f"(y) : "memory")

__device__ __forceinline__ void mbar_wait_parity(uint32_t mbar, uint32_t parity) {
    asm volatile(
        "{\n\t.reg .pred P;\n\t"
        "WL_%=:\n\t"
        "mbarrier.try_wait.parity.acquire.cta.shared::cta.b64 P, [%0], %1, 0x989680;\n\t"
        "@!P bra WL_%=;\n\t}"
        :: "r"(mbar), "r"(parity) : "memory");
}

__device__ __forceinline__ uint32_t smem_u32(const void* p) {
    uint32_t a;
    asm("{ .reg .u64 t; cvta.to.shared.u64 t, %1; cvt.u32.u64 %0, t; }" : "=r"(a) : "l"(p));
    return a;
}

__device__ __forceinline__ void ldsm_x4(uint32_t* r, uint32_t addr) {
    asm volatile("ldmatrix.sync.aligned.m8n8.x4.shared.b16 {%0,%1,%2,%3}, [%4];"
                 : "=r"(r[0]), "=r"(r[1]), "=r"(r[2]), "=r"(r[3]) : "r"(addr));
}

__device__ __forceinline__ void mma_f16(float* c, const uint32_t* a, uint32_t b0, uint32_t b1) {
    asm volatile(
        "mma.sync.aligned.m16n8k16.row.col.f32.f16.f16.f32 "
        "{%0,%1,%2,%3}, {%4,%5,%6,%7}, {%8,%9}, {%0,%1,%2,%3};"
        : "+f"(c[0]), "+f"(c[1]), "+f"(c[2]), "+f"(c[3])
        : "r"(a[0]), "r"(a[1]), "r"(a[2]), "r"(a[3]), "r"(b0), "r"(b1));
}

__device__ __forceinline__ uint32_t pack_h(float f0, float f1) {
    __half h0 = __float2half(f0), h1 = __float2half(f1);
    return ((uint32_t)__half_as_ushort(h1) << 16) | __half_as_ushort(h0);
}

// ---------------------------------------------------------------------------
// Kernel 1 (combined front-end): all three jobs are mutually independent.
// blocks [0,512):      aggregation half2 atomics into g_aggH (pre-zeroed)
// blocks [512,944):    W pack (fp16, SW128 pre-swizzled)
// blocks [944,1456):   out = bias
// ---------------------------------------------------------------------------
__global__ void front_kernel(const float* __restrict__ points,
                             const float* __restrict__ feats,
                             const float* __restrict__ weight,
                             const float* __restrict__ bias,
                             float* __restrict__ out) {
    int bid = blockIdx.x;
    if (bid < 512) {
        int gid = bid * 256 + threadIdx.x;     // (point, c2): 131072 exactly
        int c2 = gid & 31;
        int p  = gid >> 5;
        int b  = p >> 11;                      // / NPTS
        int vx = (int)points[p * 3 + 0];
        int vy = (int)points[p * 3 + 1];
        int vz = (int)points[p * 3 + 2];
        if ((unsigned)vx >= GRIDV || (unsigned)vy >= GRIDV || (unsigned)vz >= GRIDV) return;
        int row = b * NVOX + (vx * GRIDV + vy) * GRIDV + vz;
        float2 v = *(const float2*)(feats + (size_t)p * CIN + c2 * 2);
        __half2 hv = __floats2half2_rn(v.x, v.y);
        atomicAdd((__half2*)(g_aggH + (size_t)row * 128 + c2 * 4), hv);
    } else if (bid < 944) {
        int i = (bid - 512) * 256 + threadIdx.x;   // 0..110591
        int n  = i & 127;
        int k2 = (i >> 7) & 31;
        int o  = i >> 12;                          // 0..26
        float w0 = weight[(o * CIN + 2 * k2) * COUT + n];
        float w1 = weight[(o * CIN + 2 * k2 + 1) * COUT + n];
        // SW128 swizzle: chunk bits[6:4] ^= (n&7)
        uint32_t off = (uint32_t)n * 128 + (((uint32_t)k2 * 4) ^ (((uint32_t)n & 7) << 4));
        *(uint32_t*)(g_Wn + (size_t)o * 16384 + off) = pack_h(w0, w1);
    } else {
        int i = (bid - 944) * 256 + threadIdx.x;   // float4 idx < OUTN/4 = 131072
        ((float4*)out)[i] = ((const float4*)bias)[i & 31];
    }
}

// ---------------------------------------------------------------------------
// Kernel 2: fp16 1-pass mma conv. A fragments register-direct from gmem
// (prefetched 1 ahead); W via cp.async.bulk 3-stage ring.
// grid = NTILE*NGRP = 256 blocks, 2 CTA/SM. Warp (wm 0..3, wn 0..1).
// Epilogue: red.global.add.v2.f32 into bias-initialized out.
// ---------------------------------------------------------------------------
#define NSTG   3
#define WBUF   16384                   // per-offset W (fp16, swizzled)
#define SMO_W  0
#define SMO_VOX (NSTG * WBUF)          // 49152
#define SMO_MBAR (SMO_VOX + 3 * TM * 4)  // 49920
#define SMEM_TOTAL (SMO_MBAR + 64)     // 49984

__global__ __launch_bounds__(256, 2)
void conv_mma_kernel(const float* __restrict__ points, float* __restrict__ out) {
    extern __shared__ __align__(1024) unsigned char smem[];
    int* svox = (int*)(smem + SMO_VOX);

    const int tid  = threadIdx.x;
    const int warp = tid >> 5;
    const int lane = tid & 31;
    const int wm   = warp >> 1;      // 0..3 : rows [wm*16, +16)
    const int wn   = warp & 1;       // 0..1 : couts [wn*64, +64)
    const int grp  = lane >> 2;      // 0..7
    const int tig  = lane & 3;       // 0..3

    const int g    = blockIdx.x & 3;         // offset group
    const int tile = blockIdx.x >> 2;        // point tile
    const int o0   = g * 7;
    const int OE   = (g == 3) ? 6 : 7;       // offsets in this group
    const int p0   = tile * TM;
    const int b    = p0 >> 11;               // / NPTS

    if (tid < TM) {
        int p = p0 + tid;
        svox[tid]          = (int)points[p * 3 + 0];
        svox[TM + tid]     = (int)points[p * 3 + 1];
        svox[2 * TM + tid] = (int)points[p * 3 + 2];
    }
    __syncthreads();

    const uint32_t sb = smem_u32(smem);

    if (tid == 0) {
        MBAR_INIT(sb + SMO_MBAR,      1);
        MBAR_INIT(sb + SMO_MBAR + 8,  1);
        MBAR_INIT(sb + SMO_MBAR + 16, 1);
    }
    __syncthreads();

    // ---- this thread's two A rows (points wm*16+grp and +8) ----
    const int mA = wm * 16 + grp;
    const int vxA = svox[mA],     vyA = svox[TM + mA],     vzA = svox[2 * TM + mA];
    const int vxB = svox[mA + 8], vyB = svox[TM + mA + 8], vzB = svox[2 * TM + mA + 8];
    const int bNV = b * NVOX;

    // direct-gather A fragments for offset o into 16 regs
    auto prefetchA = [&](int o, uint32_t* a) {
        int dx = o / 9 - 1, dy = (o / 3) % 3 - 1, dz = o % 3 - 1;
        int nxA = vxA + dx, nyA = vyA + dy, nzA = vzA + dz;
        int nxB = vxB + dx, nyB = vyB + dy, nzB = vzB + dz;
        int rA = ((unsigned)nxA < GRIDV && (unsigned)nyA < GRIDV && (unsigned)nzA < GRIDV)
               ? bNV + (nxA * GRIDV + nyA) * GRIDV + nzA : ZROW;
        int rB = ((unsigned)nxB < GRIDV && (unsigned)nyB < GRIDV && (unsigned)nzB < GRIDV)
               ? bNV + (nxB * GRIDV + nyB) * GRIDV + nzB : ZROW;
        const unsigned char* baseA = g_aggH + (size_t)rA * 128 + tig * 4;
        const unsigned char* baseB = g_aggH + (size_t)rB * 128 + tig * 4;
        #pragma unroll
        for (int kk = 0; kk < 4; kk++) {
            a[kk*4+0] = *(const uint32_t*)(baseA + kk * 32);
            a[kk*4+1] = *(const uint32_t*)(baseB + kk * 32);
            a[kk*4+2] = *(const uint32_t*)(baseA + kk * 32 + 16);
            a[kk*4+3] = *(const uint32_t*)(baseB + kk * 32 + 16);
        }
    };
    auto issueW = [&](int o, int s) {
        if (tid == 0) {
            uint32_t mb = sb + SMO_MBAR + s * 8;
            MBAR_EXPECT_TX(mb, WBUF);
            BULK_G2S(sb + SMO_W + s * WBUF, g_Wn + (size_t)o * WBUF, WBUF, mb);
        }
    };

    float c[32];
    #pragma unroll
    for (int i = 0; i < 32; i++) c[i] = 0.f;

    // ---- prologue: W stages 0,1 + A for first offset ----
    issueW(o0, 0);
    issueW(o0 + 1, 1);
    uint32_t aCur[16], aNxt[16];
    prefetchA(o0, aCur);

    // ---- B ldmatrix lane addressing (128B rows, SW128) ----
    const int bc   = lane & 7;
    const uint32_t bXor = (uint32_t)bc << 4;
    const uint32_t bRow0 = sb + SMO_W
        + (uint32_t)(wn * 64 + ((lane >> 4) & 1) * 8 + bc) * 128;
    const uint32_t bKsel = ((lane >> 3) & 1) * 16;

    for (int i = 0; i < OE; i++) {
        const int s = i % 3;

        // W prefetch 2 ahead; A prefetch 1 ahead (registers)
        if (i + 2 < OE) issueW(o0 + i + 2, (i + 2) % 3);
        if (i + 1 < OE) prefetchA(o0 + i + 1, aNxt);

        // wait for this stage's W
        mbar_wait_parity(sb + SMO_MBAR + s * 8, (uint32_t)((i / 3) & 1));

        // ---- 1-pass mma over 4 k-steps (A in registers) ----
        const uint32_t bB = bRow0 + (uint32_t)s * WBUF;
        #pragma unroll
        for (int kk = 0; kk < 4; kk++) {
            const uint32_t kx = ((uint32_t)(kk * 32) + bKsel) ^ bXor;
            #pragma unroll
            for (int j = 0; j < 4; j++) {
                uint32_t bh[4];
                ldsm_x4(bh, bB + j * 2048 + kx);
                mma_f16(&c[(2 * j) * 4],     &aCur[kk * 4], bh[0], bh[1]);
                mma_f16(&c[(2 * j + 1) * 4], &aCur[kk * 4], bh[2], bh[3]);
            }
        }

        // rotate A registers
        #pragma unroll
        for (int q = 0; q < 16; q++) aCur[q] = aNxt[q];

        __syncthreads();   // stage-s smem reads done before its next producer
    }

    // ---- epilogue: vector float2 reductions into bias-initialized out ----
    const int r0 = p0 + wm * 16 + grp;
    #pragma unroll
    for (int f = 0; f < 8; f++) {
        int col = wn * 64 + f * 8 + tig * 2;
        const float* cc = &c[f * 4];
        float* oA = out + (size_t)r0 * COUT + col;
        float* oB = out + (size_t)(r0 + 8) * COUT + col;
        RED_ADD_V2(oA, cc[0], cc[1]);
        RED_ADD_V2(oB, cc[2], cc[3]);
    }
}

// ---------------------------------------------------------------------------
// Kernel 3: restore the aggH==0 invariant for the next launch (runs after
// conv, the only reader). 27656 float4 = (NROWS+1)*128 bytes.
// ---------------------------------------------------------------------------
__global__ void cleanup_kernel() {
    int t = blockIdx.x * blockDim.x + threadIdx.x;
    if (t < (NROWS + 1) * 128 / 16)
        ((float4*)g_aggH)[t] = make_float4(0.f, 0.f, 0.f, 0.f);
}

// ---------------------------------------------------------------------------
extern "C" void kernel_launch(void* const* d_in, const int* in_sizes, int n_in,
                              void* d_out, int out_size) {
    const float* points  = (const float*)d_in[0];   // (B, N, 3)
    const float* feats   = (const float*)d_in[1];   // (B, N, CIN)
    const float* weight  = (const float*)d_in[2];   // (3,3,3,CIN,COUT)
    const float* bias    = (const float*)d_in[3];   // (COUT)
    float* out = (float*)d_out;                     // (B, N, COUT)

    cudaFuncSetAttribute(conv_mma_kernel,
                         cudaFuncAttributeMaxDynamicSharedMemorySize, SMEM_TOTAL);

    // 1) combined front-end: aggregation (into pre-zeroed aggH) + W pack + out=bias
    front_kernel<<<1456, 256>>>(points, feats, weight, bias, out);
    // 2) fp16 1-pass conv, register-direct A + bulk W, red.v2 epilogue
    conv_mma_kernel<<<NTILE * NGRP, 256, SMEM_TOTAL>>>(points, out);
    // 3) re-zero aggH (maintains entry invariant for the next launch/replay)
    cleanup_kernel<<<109, 256>>>();
}

// round 17
// speedup vs baseline: 1.0056x; 1.0056x over previous
#include <cuda_runtime.h>
#include <cuda_fp16.h>
#include <cstdint>

// Problem constants
#define BATCH   2
#define NPTS    2048
#define CIN     64
#define COUT    128
#define GRIDV   12
#define NVOX    (GRIDV*GRIDV*GRIDV)   // 1728
#define NOFF    27
#define NGRP    4                     // offset groups: 7/7/7/6
#define TM      128                   // points per conv block
#define NTILE   (BATCH*NPTS/TM)       // 32 point tiles
#define NROWS   (BATCH*NVOX)          // 3456
#define ZROW    NROWS                 // dedicated zero row index
#define OUTN    (BATCH*NPTS*COUT)     // 524288

// Scratch (device globals; no allocation allowed).
// INVARIANT: g_aggH is all-zero at kernel_launch entry (module-load zero-init;
// cleanup_kernel restores it at the END of every launch after conv completes).
__device__ __align__(16) unsigned char g_aggH[(NROWS + 1) * 128];  // fp16 agg rows (+zero row)
// W per offset: 16KB = [n][128B row], fp16, SW128-PRE-SWIZZLED
__device__ __align__(1024) unsigned char g_Wn[NOFF * 16384];

// ---------------------------------------------------------------------------
// Helpers
// ---------------------------------------------------------------------------
#define MBAR_INIT(a, c) \
    asm volatile("mbarrier.init.shared.b64 [%0], %1;" :: "r"(a), "r"(c) : "memory")
#define MBAR_EXPECT_TX(a, b) \
    asm volatile("mbarrier.arrive.expect_tx.shared.b64 _, [%0], %1;" :: "r"(a), "r"(b) : "memory")
#define BULK_G2S(dst, src, bytes, mbar) \
    asm volatile("cp.async.bulk.shared::cluster.global.mbarrier::complete_tx::bytes [%0], [%1], %2, [%3];" \
                 :: "r"(dst), "l"(src), "r"(bytes), "r"(mbar) : "memory")
#define RED_ADD_V2(addr, x, y) \
    asm volatile("red.global.add.v2.f32 [%0], {%1, %2};" :: "l"(addr), "f"(x), "f"(y) : "memory")

__device__ __forceinline__ void mbar_wait_parity(uint32_t mbar, uint32_t parity) {
    asm volatile(
        "{\n\t.reg .pred P;\n\t"
        "WL_%=:\n\t"
        "mbarrier.try_wait.parity.acquire.cta.shared::cta.b64 P, [%0], %1, 0x989680;\n\t"
        "@!P bra WL_%=;\n\t}"
        :: "r"(mbar), "r"(parity) : "memory");
}

__device__ __forceinline__ uint32_t smem_u32(const void* p) {
    uint32_t a;
    asm("{ .reg .u64 t; cvta.to.shared.u64 t, %1; cvt.u32.u64 %0, t; }" : "=r"(a) : "l"(p));
    return a;
}

__device__ __forceinline__ void ldsm_x4(uint32_t* r, uint32_t addr) {
    asm volatile("ldmatrix.sync.aligned.m8n8.x4.shared.b16 {%0,%1,%2,%3}, [%4];"
                 : "=r"(r[0]), "=r"(r[1]), "=r"(r[2]), "=r"(r[3]) : "r"(addr));
}

__device__ __forceinline__ void mma_f16(float* c, const uint32_t* a, uint32_t b0, uint32_t b1) {
    asm volatile(
        "mma.sync.aligned.m16n8k16.row.col.f32.f16.f16.f32 "
        "{%0,%1,%2,%3}, {%4,%5,%6,%7}, {%8,%9}, {%0,%1,%2,%3};"
        : "+f"(c[0]), "+f"(c[1]), "+f"(c[2]), "+f"(c[3])
        : "r"(a[0]), "r"(a[1]), "r"(a[2]), "r"(a[3]), "r"(b0), "r"(b1));
}

__device__ __forceinline__ uint32_t pack_h(float f0, float f1) {
    __half h0 = __float2half(f0), h1 = __float2half(f1);
    return ((uint32_t)__half_as_ushort(h1) << 16) | __half_as_ushort(h0);
}

// ---------------------------------------------------------------------------
// Kernel 1 (combined front-end): independent jobs by block range.
// blocks [0,512):      aggregation half2 atomics into g_aggH (pre-zeroed)
// blocks [512,944):    W pack (fp16, SW128 pre-swizzled)
// blocks [944,1456):   out = bias
// ---------------------------------------------------------------------------
__global__ void front_kernel(const float* __restrict__ points,
                             const float* __restrict__ feats,
                             const float* __restrict__ weight,
                             const float* __restrict__ bias,
                             float* __restrict__ out) {
    int bid = blockIdx.x;
    if (bid < 512) {
        int gid = bid * 256 + threadIdx.x;     // (point, c2): 131072 exactly
        int c2 = gid & 31;
        int p  = gid >> 5;
        int b  = p >> 11;                      // / NPTS
        int vx = (int)points[p * 3 + 0];
        int vy = (int)points[p * 3 + 1];
        int vz = (int)points[p * 3 + 2];
        if ((unsigned)vx >= GRIDV || (unsigned)vy >= GRIDV || (unsigned)vz >= GRIDV) return;
        int row = b * NVOX + (vx * GRIDV + vy) * GRIDV + vz;
        float2 v = *(const float2*)(feats + (size_t)p * CIN + c2 * 2);
        __half2 hv = __floats2half2_rn(v.x, v.y);
        atomicAdd((__half2*)(g_aggH + (size_t)row * 128 + c2 * 4), hv);
    } else if (bid < 944) {
        int i = (bid - 512) * 256 + threadIdx.x;   // 0..110591
        int n  = i & 127;
        int k2 = (i >> 7) & 31;
        int o  = i >> 12;                          // 0..26
        float w0 = weight[(o * CIN + 2 * k2) * COUT + n];
        float w1 = weight[(o * CIN + 2 * k2 + 1) * COUT + n];
        // SW128 swizzle: chunk bits[6:4] ^= (n&7)
        uint32_t off = (uint32_t)n * 128 + (((uint32_t)k2 * 4) ^ (((uint32_t)n & 7) << 4));
        *(uint32_t*)(g_Wn + (size_t)o * 16384 + off) = pack_h(w0, w1);
    } else {
        int i = (bid - 944) * 256 + threadIdx.x;   // float4 idx < OUTN/4 = 131072
        ((float4*)out)[i] = ((const float4*)bias)[i & 31];
    }
}

// ---------------------------------------------------------------------------
// Kernel 2: fp16 1-pass mma conv, BARRIER-FREE main loop.
// All <=7 W tiles pre-staged in smem (7 single-use mbarriers, never rewritten);
// each warp free-runs: mbar_wait(i) -> 16 ldsm -> 32 mma, A register-prefetched.
// grid = NTILE*NGRP = 128 blocks x 512 threads (16 warps, 1 CTA/SM).
// Tile 128 points x 128 couts. Warp (wm 0..7, wn 0..1): 16 rows x 64 couts.
// Epilogue: red.global.add.v2.f32 into bias-initialized out.
// ---------------------------------------------------------------------------
#define NSTG   7
#define WBUF   16384                     // per-offset W (fp16, swizzled)
#define SMO_W  0
#define SMO_VOX (NSTG * WBUF)            // 114688
#define SMO_MBAR (SMO_VOX + 3 * TM * 4)  // 116224
#define SMEM_TOTAL (SMO_MBAR + 64)       // 116288

__global__ __launch_bounds__(512, 1)
void conv_mma_kernel(const float* __restrict__ points, float* __restrict__ out) {
    extern __shared__ __align__(1024) unsigned char smem[];
    int* svox = (int*)(smem + SMO_VOX);

    const int tid  = threadIdx.x;
    const int warp = tid >> 5;
    const int lane = tid & 31;
    const int wm   = warp >> 1;      // 0..7 : rows [wm*16, +16)
    const int wn   = warp & 1;       // 0..1 : couts [wn*64, +64)
    const int grp  = lane >> 2;      // 0..7
    const int tig  = lane & 3;       // 0..3

    const int g    = blockIdx.x & 3;         // offset group
    const int tile = blockIdx.x >> 2;        // point tile
    const int o0   = g * 7;
    const int OE   = (g == 3) ? 6 : 7;       // offsets in this group
    const int p0   = tile * TM;
    const int b    = p0 >> 11;               // / NPTS

    if (tid < TM) {
        int p = p0 + tid;
        svox[tid]          = (int)points[p * 3 + 0];
        svox[TM + tid]     = (int)points[p * 3 + 1];
        svox[2 * TM + tid] = (int)points[p * 3 + 2];
    }
    const uint32_t sb = smem_u32(smem);
    if (tid == 0) {
        #pragma unroll
        for (int s = 0; s < NSTG; s++) MBAR_INIT(sb + SMO_MBAR + s * 8, 1);
    }
    __syncthreads();

    // ---- prologue: issue ALL W bulk copies (single-use stages) ----
    if (tid == 0) {
        for (int s = 0; s < OE; s++) {
            uint32_t mb = sb + SMO_MBAR + s * 8;
            MBAR_EXPECT_TX(mb, WBUF);
            BULK_G2S(sb + SMO_W + s * WBUF, g_Wn + (size_t)(o0 + s) * WBUF, WBUF, mb);
        }
    }

    // ---- this thread's two A rows (points wm*16+grp and +8) ----
    const int mA = wm * 16 + grp;
    const int vxA = svox[mA],     vyA = svox[TM + mA],     vzA = svox[2 * TM + mA];
    const int vxB = svox[mA + 8], vyB = svox[TM + mA + 8], vzB = svox[2 * TM + mA + 8];
    const int bNV = b * NVOX;

    // direct-gather A fragments for offset o into 16 regs
    auto prefetchA = [&](int o, uint32_t* a) {
        int dx = o / 9 - 1, dy = (o / 3) % 3 - 1, dz = o % 3 - 1;
        int nxA = vxA + dx, nyA = vyA + dy, nzA = vzA + dz;
        int nxB = vxB + dx, nyB = vyB + dy, nzB = vzB + dz;
        int rA = ((unsigned)nxA < GRIDV && (unsigned)nyA < GRIDV && (unsigned)nzA < GRIDV)
               ? bNV + (nxA * GRIDV + nyA) * GRIDV + nzA : ZROW;
        int rB = ((unsigned)nxB < GRIDV && (unsigned)nyB < GRIDV && (unsigned)nzB < GRIDV)
               ? bNV + (nxB * GRIDV + nyB) * GRIDV + nzB : ZROW;
        const unsigned char* baseA = g_aggH + (size_t)rA * 128 + tig * 4;
        const unsigned char* baseB = g_aggH + (size_t)rB * 128 + tig * 4;
        #pragma unroll
        for (int kk = 0; kk < 4; kk++) {
            a[kk*4+0] = *(const uint32_t*)(baseA + kk * 32);
            a[kk*4+1] = *(const uint32_t*)(baseB + kk * 32);
            a[kk*4+2] = *(const uint32_t*)(baseA + kk * 32 + 16);
            a[kk*4+3] = *(const uint32_t*)(baseB + kk * 32 + 16);
        }
    };

    float c[32];
    #pragma unroll
    for (int i = 0; i < 32; i++) c[i] = 0.f;

    uint32_t aCur[16], aNxt[16];
    prefetchA(o0, aCur);

    // ---- B ldmatrix lane addressing (128B rows, SW128) ----
    const int bc   = lane & 7;
    const uint32_t bXor = (uint32_t)bc << 4;
    const uint32_t bRow0 = sb + SMO_W
        + (uint32_t)(wn * 64 + ((lane >> 4) & 1) * 8 + bc) * 128;
    const uint32_t bKsel = ((lane >> 3) & 1) * 16;

    // ---- barrier-free main loop: each warp free-runs through stages ----
    for (int i = 0; i < OE; i++) {
        if (i + 1 < OE) prefetchA(o0 + i + 1, aNxt);

        mbar_wait_parity(sb + SMO_MBAR + i * 8, 0u);

        const uint32_t bB = bRow0 + (uint32_t)i * WBUF;
        #pragma unroll
        for (int kk = 0; kk < 4; kk++) {
            const uint32_t kx = ((uint32_t)(kk * 32) + bKsel) ^ bXor;
            #pragma unroll
            for (int j = 0; j < 4; j++) {
                uint32_t bh[4];
                ldsm_x4(bh, bB + j * 2048 + kx);
                mma_f16(&c[(2 * j) * 4],     &aCur[kk * 4], bh[0], bh[1]);
                mma_f16(&c[(2 * j + 1) * 4], &aCur[kk * 4], bh[2], bh[3]);
            }
        }

        #pragma unroll
        for (int q = 0; q < 16; q++) aCur[q] = aNxt[q];
    }

    // ---- epilogue: vector float2 reductions into bias-initialized out ----
    const int r0 = p0 + wm * 16 + grp;
    #pragma unroll
    for (int f = 0; f < 8; f++) {
        int col = wn * 64 + f * 8 + tig * 2;
        const float* cc = &c[f * 4];
        float* oA = out + (size_t)r0 * COUT + col;
        float* oB = out + (size_t)(r0 + 8) * COUT + col;
        RED_ADD_V2(oA, cc[0], cc[1]);
        RED_ADD_V2(oB, cc[2], cc[3]);
    }
}

// ---------------------------------------------------------------------------
// Kernel 3: restore aggH==0 invariant (runs after conv, the only reader).
// ---------------------------------------------------------------------------
__global__ void cleanup_kernel() {
    int t = blockIdx.x * blockDim.x + threadIdx.x;
    if (t < (NROWS + 1) * 128 / 16)
        ((float4*)g_aggH)[t] = make_float4(0.f, 0.f, 0.f, 0.f);
}

// ---------------------------------------------------------------------------
extern "C" void kernel_launch(void* const* d_in, const int* in_sizes, int n_in,
                              void* d_out, int out_size) {
    const float* points  = (const float*)d_in[0];   // (B, N, 3)
    const float* feats   = (const float*)d_in[1];   // (B, N, CIN)
    const float* weight  = (const float*)d_in[2];   // (3,3,3,CIN,COUT)
    const float* bias    = (const float*)d_in[3];   // (COUT)
    float* out = (float*)d_out;                     // (B, N, COUT)

    cudaFuncSetAttribute(conv_mma_kernel,
                         cudaFuncAttributeMaxDynamicSharedMemorySize, SMEM_TOTAL);

    // 1) combined front-end: aggregation + W pack + out=bias
    front_kernel<<<1456, 256>>>(points, feats, weight, bias, out);
    // 2) fp16 1-pass conv, barrier-free loop, red.v2 epilogue
    conv_mma_kernel<<<NTILE * NGRP, 512, SMEM_TOTAL>>>(points, out);
    // 3) re-zero aggH (maintains entry invariant for the next launch/replay)
    cleanup_kernel<<<109, 256>>>();
}